// round 8
// baseline (speedup 1.0000x reference)
#include <cuda_runtime.h>
#include <cstdint>
#include <cstring>
#include <cmath>
#include <cstdio>

// ============================================================================
// np.random.default_rng(42) replication.
// Primary path: DIRECT raw PCG64 state/inc (published in numpy docs for
// seed 42), core verified against the first two random() doubles:
//   0.7739560485559633, 0.4388784397520523
// Fallback: 512-variant SeedSequence search (prior rounds).
// On total failure: print diagnostics to stderr, do no work (rc=1 surfaces).
// ============================================================================
#define MAXOPS 64
struct OpsParam {
    int n;
    int type[MAXOPS];
    int a[MAXOPS];
    int b[MAXOPS];
    int c[MAXOPS];
};

typedef unsigned __int128 hu128;

struct Pcg {
    hu128 state, inc;
    int alg, out_mode;   // alg: 0 XSL-RR, 1 DXSM ; out_mode: 0 step-then-out
    int has32;
    uint32_t buf32;

    static hu128 defmul() {
        return (((hu128)0x2360ed051fc65da4ULL) << 64) | 0x4385df649fccf645ULL;
    }
    void stepv() {
        if (alg == 0) state = state * defmul() + inc;
        else          state = state * (hu128)0xda942042e4dd58b5ULL + inc;
    }
    uint64_t out_xslrr() const {
        uint64_t hi = (uint64_t)(state >> 64);
        uint64_t lo = (uint64_t)state;
        uint64_t x = hi ^ lo;
        unsigned rot = (unsigned)(state >> 122);
        return (x >> rot) | (x << ((64u - rot) & 63u));
    }
    uint64_t out_dxsm() const {
        uint64_t hi = (uint64_t)(state >> 64);
        uint64_t lo = (uint64_t)state | 1ULL;
        hi ^= hi >> 32;
        hi *= 0xda942042e4dd58b5ULL;
        hi ^= hi >> 48;
        hi *= lo;
        return hi;
    }
    uint64_t outv() const { return alg == 0 ? out_xslrr() : out_dxsm(); }
    uint64_t next64() {
        if (out_mode == 0) { stepv(); return outv(); }
        uint64_t r = outv(); stepv(); return r;
    }
    uint32_t next32() {
        if (has32) { has32 = 0; return buf32; }
        uint64_t n = next64();
        has32 = 1;
        buf32 = (uint32_t)(n >> 32);
        return (uint32_t)(n & 0xffffffffu);
    }
    double next_double() {
        return (double)(next64() >> 11) * (1.0 / 9007199254740992.0);
    }
    // integers(0,n): buffered bounded_lemire_uint32 on next_uint32
    uint32_t lemire32(uint32_t rng) {
        uint32_t rng_excl = rng + 1u;
        uint64_t m = (uint64_t)next32() * (uint64_t)rng_excl;
        uint32_t leftover = (uint32_t)m;
        if (leftover < rng_excl) {
            uint32_t threshold = (uint32_t)((0xFFFFFFFFu - rng) % rng_excl);
            while (leftover < threshold) {
                m = (uint64_t)next32() * (uint64_t)rng_excl;
                leftover = (uint32_t)m;
            }
        }
        return (uint32_t)(m >> 32);
    }
    // shuffle(): random_interval masked rejection via next_uint32
    uint64_t random_interval(uint64_t mx) {
        if (mx == 0) return 0;
        uint64_t mask = mx;
        mask |= mask >> 1;  mask |= mask >> 2;  mask |= mask >> 4;
        mask |= mask >> 8;  mask |= mask >> 16; mask |= mask >> 32;
        uint64_t value;
        while ((value = ((uint64_t)next32() & mask)) > mx) {}
        return value;
    }
};

static hu128 parse_dec128(const char* s) {
    hu128 v = 0;
    for (; *s; s++) v = v * 10 + (hu128)(uint32_t)(*s - '0');
    return v;
}

// Published default_rng(42) raw bit-generator state (post-seeding)
static const char* S42_DEC = "274674114334540486603088602300644985544";
static const char* I42_DEC = "332724090758049132448979897138935081983";

static void seed_direct(Pcg& r, int alg, int out_mode) {
    r.alg = alg;
    r.out_mode = out_mode;
    r.state = parse_dec128(S42_DEC);
    r.inc   = parse_dec128(I42_DEC);
    r.has32 = 0;
    r.buf32 = 0;
}

// ---------------- SeedSequence fallback (512 variants, prior rounds) --------
static uint32_t hmix(uint32_t value, uint32_t& hc, uint32_t mult, int order) {
    value ^= hc;
    if (order == 0) { hc *= mult; value *= hc; }
    else            { value *= hc; hc *= mult; }
    value ^= value >> 16;
    return value;
}

static void seed_np_v(Pcg& rng, uint32_t entropy, int variant) {
    int horder  = (variant >> 3) & 1;
    int gorder  = (variant >> 7) & 1;
    uint32_t INITA = 0x43b0d7e5u, INITB = 0x8b51f9ddu;
    uint32_t MULTA = 0x931e8875u, MULTB = 0x58f38dedu;
    uint32_t MIXL  = 0xca01f9ddu, MIXR  = 0x4973f715u;
    if (variant & 16) { uint32_t t = INITA; INITA = INITB; INITB = t; }
    if (variant & 32) { uint32_t t = MULTA; MULTA = MULTB; MULTB = t; }
    if (variant & 64) { uint32_t t = MIXL;  MIXL  = MIXR;  MIXR  = t; }

    uint32_t pool[4];
    uint32_t hc = INITA;
    for (int i = 0; i < 4; i++)
        pool[i] = hmix(i < 1 ? entropy : 0u, hc, MULTA, horder);
    for (int isrc = 0; isrc < 4; isrc++)
        for (int idst = 0; idst < 4; idst++)
            if (isrc != idst) {
                uint32_t h = hmix(pool[isrc], hc, MULTA, horder);
                uint32_t r = (pool[idst] * MIXL) ^ (h * MIXR);
                r ^= r >> 16;
                pool[idst] = r;
            }
    uint32_t st[8];
    uint32_t hcb = INITB;
    for (int i = 0; i < 8; i++)
        st[i] = hmix(pool[i & 3], hcb, MULTB, gorder);

    uint64_t val[4];
    for (int k = 0; k < 4; k++) {
        if (variant & 2)
            val[k] = ((uint64_t)st[2 * k] << 32) | st[2 * k + 1];
        else
            val[k] = (uint64_t)st[2 * k] | ((uint64_t)st[2 * k + 1] << 32);
    }
    hu128 s, seq;
    if (variant & 4) {
        s   = (((hu128)val[1]) << 64) | val[0];
        seq = (((hu128)val[3]) << 64) | val[2];
    } else {
        s   = (((hu128)val[0]) << 64) | val[1];
        seq = (((hu128)val[2]) << 64) | val[3];
    }
    rng.alg = (variant >> 8) & 1;
    rng.out_mode = variant & 1;
    rng.inc = (seq << 1) | 1;
    rng.state = 0;
    rng.stepv();
    rng.state += s;
    rng.stepv();
    rng.has32 = 0;
    rng.buf32 = 0;
}

// mode: 0 -> direct(alg,out set by sub), 1 -> SeedSequence variant
struct Pick { int kind; int alg; int out_mode; int variant; };

static int find_rng(Pick& pk) {
    const double A0 = 0.7739560485559633;
    const double A1 = 0.4388784397520523;

    // Direct-state candidates: (alg, out_mode)
    for (int alg = 0; alg < 2; alg++)
        for (int om = 0; om < 2; om++) {
            Pcg r;
            seed_direct(r, alg, om);
            double d0 = r.next_double();
            double d1 = r.next_double();
            if (fabs(d0 - A0) < 1e-9 && fabs(d1 - A1) < 1e-9) {
                pk.kind = 0; pk.alg = alg; pk.out_mode = om; pk.variant = 0;
                return 1;
            }
        }

    // SeedSequence fallback across 3 anchors
    struct Anchor { uint32_t seed; double d0; };
    const Anchor anchors[3] = {
        {42u,    0.7739560485559633},
        {0u,     0.6369616873214543},
        {12345u, 0.22733602246716966},
    };
    for (int v = 0; v < 512; v++)
        for (int a = 0; a < 3; a++) {
            Pcg r;
            seed_np_v(r, anchors[a].seed, v);
            double d = r.next_double();
            if (fabs(d - anchors[a].d0) < 1e-9) {
                pk.kind = 1; pk.variant = v; pk.alg = 0; pk.out_mode = 0;
                return 1;
            }
        }
    return 0;
}

static int build_ops(OpsParam& ops) {
    Pick pk;
    if (!find_rng(pk)) {
        char buf[2048];
        int off = 0;
        off += snprintf(buf + off, sizeof(buf) - off, "DIAG direct:");
        for (int alg = 0; alg < 2; alg++)
            for (int om = 0; om < 2; om++) {
                Pcg r;
                seed_direct(r, alg, om);
                double d0 = r.next_double();
                double d1 = r.next_double();
                off += snprintf(buf + off, sizeof(buf) - off,
                                " a%dm%d=%.10g,%.10g", alg, om, d0, d1);
            }
        {
            Pcg r;
            seed_direct(r, 0, 0);
            off += snprintf(buf + off, sizeof(buf) - off,
                "\nDIAG s42 hi %016llx lo %016llx inchi %016llx inclo %016llx\n",
                (unsigned long long)(r.state >> 64), (unsigned long long)r.state,
                (unsigned long long)(r.inc >> 64), (unsigned long long)r.inc);
        }
        fputs(buf, stderr);
        fflush(stderr);
        return 0;
    }

    Pcg rng;
    if (pk.kind == 0) seed_direct(rng, pk.alg, pk.out_mode);
    else              seed_np_v(rng, 42u, pk.variant);

    ops.n = 0;
    int i = 0;
    while (i < 4 && ops.n < MAXOPS) {
        if (rng.next_double() > 0.3) {
            int kind = (int)rng.lemire32(2); // integers(0,3)
            int w    = (int)rng.lemire32(3); // integers(0,4)
            ops.type[ops.n] = 0; ops.a[ops.n] = kind; ops.b[ops.n] = w; ops.c[ops.n] = i;
            ops.n++; i++;
        } else {
            int arr[4] = {0, 1, 2, 3};
            for (int t = 3; t >= 1; t--) {
                int j = (int)rng.random_interval((uint64_t)t);
                int tmp = arr[t]; arr[t] = arr[j]; arr[j] = tmp;
            }
            ops.type[ops.n] = 1; ops.a[ops.n] = arr[0]; ops.b[ops.n] = arr[1]; ops.c[ops.n] = 0;
            ops.n++;
        }
    }
    return 1;
}

// ============================================================================
// Device: setup kernel — build U, ReM_w = Re(U^dag Z_w U), contract to coef
// z_w = sum_{p,q in 0..8} coef[p][q][w] * v01[p] * v23[q]
// ============================================================================
__device__ float4 g_coef4[162];

__device__ __forceinline__ float2 cmulf(float2 a, float2 b) {
    return make_float2(a.x * b.x - a.y * b.y, a.x * b.y + a.y * b.x);
}
__device__ __forceinline__ float2 caddf(float2 a, float2 b) {
    return make_float2(a.x + b.x, a.y + b.y);
}
__device__ __forceinline__ float Bc(int jb, int kb, int e) {
    if (jb != kb) return (e == 2) ? 0.5f : 0.0f;
    if (e == 2) return 0.0f;
    if (e == 0) return 0.5f;
    return jb ? -0.5f : 0.5f;
}

__global__ void quanv_setup(const float* __restrict__ rp, OpsParam ops) {
    __shared__ float2 U[16][16];
    __shared__ float ReM[4][16][16];
    __shared__ float G[4][9][16];
    int tid = threadIdx.x;

    if (tid < 16) {
        int col = tid;
        for (int m = 0; m < 16; m++)
            U[m][col] = make_float2(m == col ? 1.0f : 0.0f, 0.0f);
        for (int o = 0; o < ops.n; o++) {
            if (ops.type[o] == 0) {
                float th = rp[ops.c[o]];
                float ch = cosf(0.5f * th), sh = sinf(0.5f * th);
                float2 R00, R01, R10, R11;
                int kind = ops.a[o];
                if (kind == 0) {
                    R00 = make_float2(ch, 0); R11 = R00;
                    R01 = make_float2(0, -sh); R10 = R01;
                } else if (kind == 1) {
                    R00 = make_float2(ch, 0); R11 = R00;
                    R01 = make_float2(-sh, 0); R10 = make_float2(sh, 0);
                } else {
                    R00 = make_float2(ch, -sh); R11 = make_float2(ch, sh);
                    R01 = make_float2(0, 0);    R10 = make_float2(0, 0);
                }
                int bit = 1 << (3 - ops.b[o]);
                for (int m = 0; m < 16; m++) {
                    if (!(m & bit)) {
                        float2 x0 = U[m][col], x1 = U[m | bit][col];
                        U[m][col]       = caddf(cmulf(R00, x0), cmulf(R01, x1));
                        U[m | bit][col] = caddf(cmulf(R10, x0), cmulf(R11, x1));
                    }
                }
            } else {
                int cb = 1 << (3 - ops.a[o]);
                int tb = 1 << (3 - ops.b[o]);
                for (int m = 0; m < 16; m++) {
                    if ((m & cb) && !(m & tb)) {
                        float2 tmp = U[m][col];
                        U[m][col] = U[m | tb][col];
                        U[m | tb][col] = tmp;
                    }
                }
            }
        }
    }
    __syncthreads();

    for (int e = tid; e < 1024; e += blockDim.x) {
        int w = e >> 8, jk = e & 255, jj = jk >> 4, kk = jk & 15;
        int sbit = 1 << (3 - w);
        float sum = 0.0f;
        for (int m = 0; m < 16; m++) {
            float2 uj = U[m][jj], uk = U[m][kk];
            float re = uj.x * uk.x + uj.y * uk.y;
            sum += (m & sbit) ? -re : re;
        }
        ReM[w][jj][kk] = sum;
    }
    __syncthreads();

    for (int e = tid; e < 576; e += blockDim.x) {
        int w = e / 144, r = e % 144, p = r / 16, lk = r % 16;
        int jl = lk >> 2, kl = lk & 3;
        int e0 = p / 3, e1 = p % 3;
        float sum = 0.0f;
        for (int jh = 0; jh < 4; jh++)
            for (int kh = 0; kh < 4; kh++) {
                float w01 = Bc(jh >> 1, kh >> 1, e0) * Bc(jh & 1, kh & 1, e1);
                if (w01 != 0.0f)
                    sum += w01 * ReM[w][jh * 4 + jl][kh * 4 + kl];
            }
        G[w][p][lk] = sum;
    }
    __syncthreads();

    for (int m = tid; m < 81; m += blockDim.x) {
        int p = m / 9, q = m % 9;
        int e2 = q / 3, e3 = q % 3;
        float cw[4];
        for (int w = 0; w < 4; w++) {
            float sum = 0.0f;
            for (int jl = 0; jl < 4; jl++)
                for (int kl = 0; kl < 4; kl++) {
                    float w23 = Bc(jl >> 1, kl >> 1, e2) * Bc(jl & 1, kl & 1, e3);
                    if (w23 != 0.0f)
                        sum += w23 * G[w][p][jl * 4 + kl];
                }
            cw[w] = sum;
        }
        g_coef4[2 * m]     = make_float4(cw[0], cw[0], cw[1], cw[1]);
        g_coef4[2 * m + 1] = make_float4(cw[2], cw[2], cw[3], cw[3]);
    }
}

// ============================================================================
// Main kernel: 2 samples per thread, packed f32x2 math
// ============================================================================
typedef unsigned long long ull;

__device__ __forceinline__ ull pk2(float lo, float hi) {
    ull r; asm("mov.b64 %0, {%1, %2};" : "=l"(r) : "f"(lo), "f"(hi)); return r;
}
__device__ __forceinline__ void upk2(ull v, float& lo, float& hi) {
    asm("mov.b64 {%0, %1}, %2;" : "=f"(lo), "=f"(hi) : "l"(v));
}
__device__ __forceinline__ ull fma2_(ull a, ull b, ull c) {
    ull d; asm("fma.rn.f32x2 %0, %1, %2, %3;" : "=l"(d) : "l"(a), "l"(b), "l"(c)); return d;
}
__device__ __forceinline__ ull mul2_(ull a, ull b) {
    ull d; asm("mul.rn.f32x2 %0, %1, %2;" : "=l"(d) : "l"(a), "l"(b)); return d;
}
__device__ __forceinline__ ull add2_(ull a, ull b) {
    ull d; asm("add.rn.f32x2 %0, %1, %2;" : "=l"(d) : "l"(a), "l"(b)); return d;
}

__global__ void __launch_bounds__(256) quanv_main(const float4* __restrict__ x4,
                                                  float4* __restrict__ out4) {
    __shared__ ulonglong2 shc[162];
    if (threadIdx.x < 162) {
        const ulonglong2* gc = reinterpret_cast<const ulonglong2*>(g_coef4);
        shc[threadIdx.x] = gc[threadIdx.x];
    }
    __syncthreads();

    int tid = blockIdx.x * 256 + threadIdx.x;
    int t = tid & 15;
    int j = (tid >> 4) & 31;
    int i = (tid >> 9) & 31;
    int b = tid >> 14;

    int r00 = ((b * 64 + 2 * i) * 64 + 2 * j) * 16 + t;
    float4 f00 = __ldcs(&x4[r00]);
    float4 f01 = __ldcs(&x4[r00 + 16]);
    float4 f10 = __ldcs(&x4[r00 + 1024]);
    float4 f11 = __ldcs(&x4[r00 + 1040]);

    const float PI = 3.14159265358979323846f;
    float s0, c0, s1, c1;
    ull C0, S0, C1, S1, C2, S2, C3, S3;
    __sincosf(PI * f00.x, &s0, &c0); __sincosf(PI * f00.z, &s1, &c1);
    C0 = pk2(c0, c1); S0 = pk2(s0, s1);
    __sincosf(PI * f11.x, &s0, &c0); __sincosf(PI * f11.z, &s1, &c1);
    C1 = pk2(c0, c1); S1 = pk2(s0, s1);
    __sincosf(PI * f01.y, &s0, &c0); __sincosf(PI * f01.w, &s1, &c1);
    C2 = pk2(c0, c1); S2 = pk2(s0, s1);
    __sincosf(PI * f10.y, &s0, &c0); __sincosf(PI * f10.w, &s1, &c1);
    C3 = pk2(c0, c1); S3 = pk2(s0, s1);

    ull v01[9], v23[9];
    v01[0] = 0; v23[0] = 0;
    v01[1] = C1; v01[2] = S1; v01[3] = C0;
    v01[4] = mul2_(C0, C1); v01[5] = mul2_(C0, S1);
    v01[6] = S0; v01[7] = mul2_(S0, C1); v01[8] = mul2_(S0, S1);
    v23[1] = C3; v23[2] = S3; v23[3] = C2;
    v23[4] = mul2_(C2, C3); v23[5] = mul2_(C2, S3);
    v23[6] = S2; v23[7] = mul2_(S2, C3); v23[8] = mul2_(S2, S3);

    ull acc0 = 0, acc1 = 0, acc2 = 0, acc3 = 0;

#pragma unroll
    for (int p = 0; p < 9; p++) {
#pragma unroll
        for (int q = 0; q < 9; q++) {
            int m = p * 9 + q;
            ulonglong2 ca = shc[2 * m];
            ulonglong2 cb = shc[2 * m + 1];
            if (p == 0 && q == 0) {
                acc0 = add2_(acc0, ca.x);
                acc1 = add2_(acc1, ca.y);
                acc2 = add2_(acc2, cb.x);
                acc3 = add2_(acc3, cb.y);
            } else {
                ull tpq = (p == 0) ? v23[q] : ((q == 0) ? v01[p] : mul2_(v01[p], v23[q]));
                acc0 = fma2_(tpq, ca.x, acc0);
                acc1 = fma2_(tpq, ca.y, acc1);
                acc2 = fma2_(tpq, cb.x, acc2);
                acc3 = fma2_(tpq, cb.y, acc3);
            }
        }
    }

    float a0l, a0h, a1l, a1h, a2l, a2h, a3l, a3h;
    upk2(acc0, a0l, a0h); upk2(acc1, a1l, a1h);
    upk2(acc2, a2l, a2h); upk2(acc3, a3l, a3h);
    out4[2 * tid]     = make_float4(a0l, a1l, a2l, a3l);
    out4[2 * tid + 1] = make_float4(a0h, a1h, a2h, a3h);
}

// ============================================================================
// Launch
// ============================================================================
extern "C" void kernel_launch(void* const* d_in, const int* in_sizes, int n_in,
                              void* d_out, int out_size) {
    const float* x  = (const float*)d_in[0];
    const float* rp = (const float*)d_in[1];
    if (n_in >= 2 && in_sizes[0] == 4) {
        const float* tmp = x; x = rp; rp = tmp;
    }

    OpsParam ops;
    if (!build_ops(ops)) {
        // RNG stream unverified: do no work -> rc=1 surfaces stderr diagnostics
        return;
    }

    quanv_setup<<<1, 512>>>(rp, ops);

    int threads = 262144;
    quanv_main<<<threads / 256, 256>>>((const float4*)x, (float4*)d_out);
}